// round 1
// baseline (speedup 1.0000x reference)
#include <cuda_runtime.h>
#include <cstdint>

#define N_NODES 50000
#define N_EDGES 1600000
#define HID 64
#define DM 64
#define NV 16

// ---------------- scratch (no allocations allowed) ----------------
__device__ float g_h0[N_NODES * HID];
__device__ float g_h1[N_NODES * HID];
__device__ int   g_cnt[N_NODES];
__device__ int   g_cursor[N_NODES];
__device__ int   g_off[N_NODES + 1];
__device__ int   g_bucket[N_EDGES];
__device__ float g_A4[HID * 4];   // per j: A[j][0..2], ca[j]

// packed f32x2 helpers
#define PACK2(d, lo, hi)  asm("mov.b64 %0,{%1,%2};" : "=l"(d) : "f"(lo), "f"(hi))
#define UNPACK2(lo, hi, s) asm("mov.b64 {%0,%1},%2;" : "=f"(lo), "=f"(hi) : "l"(s))
#define FMA2(d, a, b, c)  asm("fma.rn.f32x2 %0,%1,%2,%3;" : "=l"(d) : "l"(a), "l"(b), "l"(c))

// ---------------- K0: fold Wa/We/be/vnf_mean/ba into A (64x3) + ca (64) ------
__global__ void precompute_kernel(const float* __restrict__ Wa,
                                  const float* __restrict__ ba,
                                  const float* __restrict__ We,
                                  const float* __restrict__ be,
                                  const float* __restrict__ env) {
    __shared__ float vnfm[DM];
    __shared__ float bes[HID];
    int j = threadIdx.x;   // 64 threads
    float m = 0.f;
    for (int i = 0; i < NV; i++) m += env[i * DM + j];
    vnfm[j] = m * (1.0f / NV);
    bes[j] = be[j];
    __syncthreads();

    const float* row = Wa + j * (HID + DM);
    float c = ba[j], a0 = 0.f, a1 = 0.f, a2 = 0.f;
    #pragma unroll 8
    for (int k = 0; k < HID; k++) {
        float w = row[k];
        c  = fmaf(w, bes[k], c);
        a0 = fmaf(w, We[k * 3 + 0], a0);
        a1 = fmaf(w, We[k * 3 + 1], a1);
        a2 = fmaf(w, We[k * 3 + 2], a2);
    }
    #pragma unroll 8
    for (int d = 0; d < DM; d++) c = fmaf(row[HID + d], vnfm[d], c);
    g_A4[j * 4 + 0] = a0;
    g_A4[j * 4 + 1] = a1;
    g_A4[j * 4 + 2] = a2;
    g_A4[j * 4 + 3] = c;
}

// ---------------- K1: node_fc  h0 = nf @ Wn^T + bn --------------------------
__global__ void node_fc_kernel(const float* __restrict__ nf,
                               const float* __restrict__ Wn,
                               const float* __restrict__ bn) {
    __shared__ float ws[HID * 3];
    __shared__ float bs[HID];
    int t = threadIdx.x;
    if (t < HID * 3) ws[t] = Wn[t];
    if (t < HID) bs[t] = bn[t];
    __syncthreads();
    int idx = blockIdx.x * blockDim.x + t;       // N*64 threads
    int i = idx >> 6, j = idx & 63;
    const float* r = nf + i * 3;
    float v = fmaf(ws[j * 3 + 0], r[0],
              fmaf(ws[j * 3 + 1], r[1],
              fmaf(ws[j * 3 + 2], r[2], bs[j])));
    g_h0[idx] = v;
}

// ---------------- K2: zero counters -----------------------------------------
__global__ void zero_kernel() {
    int i = blockIdx.x * blockDim.x + threadIdx.x;
    if (i < N_NODES) { g_cnt[i] = 0; g_cursor[i] = 0; }
}

// ---------------- K3: degree count ------------------------------------------
__global__ void count_kernel(const int* __restrict__ src) {
    int e = blockIdx.x * blockDim.x + threadIdx.x;   // exact E threads
    atomicAdd(&g_cnt[src[e]], 1);
}

// ---------------- K4: exclusive scan (single block) --------------------------
__global__ void scan_kernel() {
    __shared__ int sh[1024];
    __shared__ int carry;
    int t = threadIdx.x;
    if (t == 0) carry = 0;
    __syncthreads();
    for (int base = 0; base < N_NODES; base += 1024) {
        int v = (base + t < N_NODES) ? g_cnt[base + t] : 0;
        sh[t] = v;
        __syncthreads();
        for (int o = 1; o < 1024; o <<= 1) {
            int y = (t >= o) ? sh[t - o] : 0;
            __syncthreads();
            sh[t] += y;
            __syncthreads();
        }
        if (base + t < N_NODES) g_off[base + t] = carry + sh[t] - v;
        __syncthreads();
        if (t == 0) carry += sh[1023];
        __syncthreads();
    }
    if (threadIdx.x == 0) g_off[N_NODES] = carry;
}

// ---------------- K5: bucket fill (CSR adjacency) ----------------------------
__global__ void bucket_kernel(const int* __restrict__ src,
                              const int* __restrict__ dst) {
    int e = blockIdx.x * blockDim.x + threadIdx.x;
    int s = src[e];
    int p = g_off[s] + atomicAdd(&g_cursor[s], 1);
    g_bucket[p] = dst[e];
}

// ---------------- K6: GraphSAGE layer (warp per node) -------------------------
__global__ __launch_bounds__(256)
void sage_layer_kernel(const float* __restrict__ hin,
                       float* __restrict__ hout,
                       const float* __restrict__ Wself,
                       const float* __restrict__ bself,
                       const float* __restrict__ Wneigh,
                       const float* __restrict__ bneigh) {
    __shared__ float wsT[HID * HID];   // transposed: wsT[k*64+j]
    __shared__ float wnT[HID * HID];
    __shared__ float stage[8][2 * HID];
    __shared__ float bs[HID], bn2[HID];
    int t = threadIdx.x;
    for (int i = t; i < HID * HID; i += 256) {
        int j = i >> 6, k = i & 63;
        wsT[k * HID + j] = Wself[i];
        wnT[k * HID + j] = Wneigh[i];
    }
    if (t < HID) { bs[t] = bself[t]; bn2[t] = bneigh[t]; }
    __syncthreads();

    int w = t >> 5, lane = t & 31;
    for (int node = blockIdx.x * 8 + w; node < N_NODES; node += gridDim.x * 8) {
        const float* hrow = hin + node * HID;
        float slo = hrow[lane], shi = hrow[lane + 32];
        float alo = 0.f, ahi = 0.f;
        int b = g_off[node], e2 = g_off[node + 1];
        #pragma unroll 4
        for (int idx = b; idx < e2; idx++) {
            const float* hn = hin + g_bucket[idx] * HID;
            alo += hn[lane];
            ahi += hn[lane + 32];
        }
        int c = g_cnt[node];
        float inv = 1.0f / (float)(c > 0 ? c : 1);
        alo *= inv; ahi *= inv;

        stage[w][lane] = slo;       stage[w][lane + 32] = shi;
        stage[w][64 + lane] = alo;  stage[w][96 + lane] = ahi;
        __syncwarp();

        float olo = bs[lane] + bn2[lane];
        float ohi = bs[lane + 32] + bn2[lane + 32];
        #pragma unroll 8
        for (int k = 0; k < HID; k++) {
            float hv = stage[w][k];
            float nv = stage[w][64 + k];
            olo = fmaf(wsT[k * HID + lane], hv, fmaf(wnT[k * HID + lane], nv, olo));
            ohi = fmaf(wsT[k * HID + 32 + lane], hv, fmaf(wnT[k * HID + 32 + lane], nv, ohi));
        }
        hout[node * HID + lane]      = fmaxf(olo, 0.f);
        hout[node * HID + 32 + lane] = fmaxf(ohi, 0.f);
        __syncwarp();
    }
}

// ---------------- K7: edge scorer (thread per edge, f32x2 FMA) ----------------
__global__ __launch_bounds__(256)
void edge_score_kernel(const float* __restrict__ ef,
                       const float* __restrict__ W1,
                       const float* __restrict__ b1,
                       const float* __restrict__ W2,
                       const float* __restrict__ b2,
                       float* __restrict__ out) {
    __shared__ __align__(16) float W1s[HID * HID];   // 16 KB
    __shared__ float4 A4s[HID];
    __shared__ float b1s[HID], w2s[HID];
    __shared__ float b2s;
    int t = threadIdx.x;
    for (int i = t; i < HID * HID; i += 256) W1s[i] = W1[i];
    if (t < HID) {
        A4s[t] = ((const float4*)g_A4)[t];
        b1s[t] = b1[t];
        w2s[t] = W2[t];
    }
    if (t == 0) b2s = b2[0];
    __syncthreads();

    int e = blockIdx.x * blockDim.x + t;   // grid covers E exactly
    float x = ef[e * 3 + 0], y = ef[e * 3 + 1], z = ef[e * 3 + 2];

    // a = relu(A*ef + ca), packed pairwise into f32x2
    unsigned long long a2[32];
    #pragma unroll
    for (int m = 0; m < 32; m++) {
        float4 c0 = A4s[2 * m], c1 = A4s[2 * m + 1];
        float lo = fmaxf(fmaf(c0.x, x, fmaf(c0.y, y, fmaf(c0.z, z, c0.w))), 0.f);
        float hi = fmaxf(fmaf(c1.x, x, fmaf(c1.y, y, fmaf(c1.z, z, c1.w))), 0.f);
        PACK2(a2[m], lo, hi);
    }

    float score = b2s;
    const float zf = 0.0f;
    for (int j = 0; j < HID; j += 2) {
        unsigned long long acc0, acc1;
        PACK2(acc0, b1s[j], zf);
        PACK2(acc1, b1s[j + 1], zf);
        const ulonglong2* r0 = (const ulonglong2*)(W1s + j * HID);
        const ulonglong2* r1 = (const ulonglong2*)(W1s + (j + 1) * HID);
        #pragma unroll
        for (int kk = 0; kk < 16; kk++) {
            ulonglong2 w0 = r0[kk];
            ulonglong2 w1 = r1[kk];
            FMA2(acc0, w0.x, a2[2 * kk], acc0);
            FMA2(acc0, w0.y, a2[2 * kk + 1], acc0);
            FMA2(acc1, w1.x, a2[2 * kk], acc1);
            FMA2(acc1, w1.y, a2[2 * kk + 1], acc1);
        }
        float l0, h0, l1, h1;
        UNPACK2(l0, h0, acc0);
        UNPACK2(l1, h1, acc1);
        float s0 = fmaxf(l0 + h0, 0.f);
        float s1 = fmaxf(l1 + h1, 0.f);
        score = fmaf(s0, w2s[j], score);
        score = fmaf(s1, w2s[j + 1], score);
    }
    out[e] = score;
}

// ---------------- launch ------------------------------------------------------
extern "C" void kernel_launch(void* const* d_in, const int* in_sizes, int n_in,
                              void* d_out, int out_size) {
    const float* node_feats = (const float*)d_in[0];
    const float* edge_feats = (const float*)d_in[1];
    const float* env        = (const float*)d_in[2];
    const int*   edge_index = (const int*)d_in[3];
    const float* Wn  = (const float*)d_in[4];
    const float* bn  = (const float*)d_in[5];
    const float* We  = (const float*)d_in[6];
    const float* be  = (const float*)d_in[7];
    const float* Wself  = (const float*)d_in[8];
    const float* bself  = (const float*)d_in[9];
    const float* Wneigh = (const float*)d_in[10];
    const float* bneigh = (const float*)d_in[11];
    const float* Wa  = (const float*)d_in[12];
    const float* ba  = (const float*)d_in[13];
    const float* W1  = (const float*)d_in[14];
    const float* b1  = (const float*)d_in[15];
    const float* W2  = (const float*)d_in[16];
    const float* b2  = (const float*)d_in[17];

    float* out_scores = (float*)d_out;             // [E]
    float* out_h = (float*)d_out + N_EDGES;        // [N, H]

    const int* src = edge_index;
    const int* dst = edge_index + N_EDGES;

    float* h0p; cudaGetSymbolAddress((void**)&h0p, g_h0);
    float* h1p; cudaGetSymbolAddress((void**)&h1p, g_h1);

    precompute_kernel<<<1, 64>>>(Wa, ba, We, be, env);
    node_fc_kernel<<<(N_NODES * HID) / 256, 256>>>(node_feats, Wn, bn);
    zero_kernel<<<(N_NODES + 255) / 256, 256>>>();
    count_kernel<<<N_EDGES / 256, 256>>>(src);
    scan_kernel<<<1, 1024>>>();
    bucket_kernel<<<N_EDGES / 256, 256>>>(src, dst);

    sage_layer_kernel<<<(N_NODES + 7) / 8, 256>>>(h0p, h1p,
        Wself, bself, Wneigh, bneigh);
    sage_layer_kernel<<<(N_NODES + 7) / 8, 256>>>(h1p, out_h,
        Wself + HID * HID, bself + HID, Wneigh + HID * HID, bneigh + HID);

    edge_score_kernel<<<N_EDGES / 256, 256>>>(edge_feats, W1, b1, W2, b2, out_scores);
}